// round 16
// baseline (speedup 1.0000x reference)
#include <cuda_runtime.h>
#include <cuda_fp16.h>
#include <cstdint>
#include <math.h>

#define Bq 4
#define SEQ 2048
#define CH 768
#define NH 12
#define HD 64
#define NTOK (Bq*SEQ)

#define KOFF 0
#define VOFF 6291456
#define QOFF 12582912

__device__ __forceinline__ void ldm_x4(unsigned int* r, const void* p) {
    unsigned int a = (unsigned int)__cvta_generic_to_shared(p);
    asm volatile("ldmatrix.sync.aligned.m8n8.x4.shared.b16 {%0,%1,%2,%3}, [%4];"
                 : "=r"(r[0]), "=r"(r[1]), "=r"(r[2]), "=r"(r[3]) : "r"(a));
}
__device__ __forceinline__ void ldm_x2(unsigned int* r, const void* p) {
    unsigned int a = (unsigned int)__cvta_generic_to_shared(p);
    asm volatile("ldmatrix.sync.aligned.m8n8.x2.shared.b16 {%0,%1}, [%2];"
                 : "=r"(r[0]), "=r"(r[1]) : "r"(a));
}
__device__ __forceinline__ void mma16816(float* c, const unsigned int* a,
                                         const unsigned int* b) {
    asm volatile("mma.sync.aligned.m16n8k16.row.col.f32.f16.f16.f32 "
                 "{%0,%1,%2,%3},{%4,%5,%6,%7},{%8,%9},{%0,%1,%2,%3};"
                 : "+f"(c[0]), "+f"(c[1]), "+f"(c[2]), "+f"(c[3])
                 : "r"(a[0]), "r"(a[1]), "r"(a[2]), "r"(a[3]), "r"(b[0]), "r"(b[1]));
}
__device__ __forceinline__ unsigned int pack_h2(float a, float b) {
    __half2 t = __floats2half2_rn(a, b);
    return *(unsigned int*)&t;
}
__device__ __forceinline__ void cp16(void* dst, const void* src) {
    unsigned int d = (unsigned int)__cvta_generic_to_shared(dst);
    asm volatile("cp.async.ca.shared.global [%0], [%1], 16;" :: "r"(d), "l"(src) : "memory");
}
#define CP_COMMIT() asm volatile("cp.async.commit_group;" ::: "memory")
#define CP_WAIT0()  asm volatile("cp.async.wait_group 0;" ::: "memory")

// ============ K1: QKV projection, one 6-head group (proven R12) ============
__global__ __launch_bounds__(256) void qkv_kernel(
    const float* __restrict__ x, const float* __restrict__ w,
    char* __restrict__ dout, int grp)
{
    extern __shared__ __align__(16) char sm[];
    int tid = threadIdx.x, warp = tid >> 5, lane = tid & 31;
    int mw = warp >> 2, nw = warp & 3;
    int t0 = blockIdx.x * 64;
    int bhg = blockIdx.y, b = bhg / 6, hg = bhg % 6, h = grp * 6 + hg;

    int rX[3], cX[3], rW[9], cW[9], wr[9];
#pragma unroll
    for (int i = 0; i < 3; i++) { int e = tid + 256 * i; rX[i] = e / 12; cX[i] = (e % 12) << 2; }
#pragma unroll
    for (int i = 0; i < 9; i++) {
        int e = tid + 256 * i; int r = e / 12; rW[i] = r; cW[i] = (e % 12) << 2;
        wr[i] = (r < 64) ? (h * HD + r) : (r < 128) ? (CH + h * HD + r - 64)
                                                    : (2 * CH + h * HD + r - 128);
    }

    float4 pX[3], pW[9];
#pragma unroll
    for (int i = 0; i < 3; i++) pX[i] = *(const float4*)&x[(b * SEQ + t0 + rX[i]) * CH + cX[i]];
#pragma unroll
    for (int i = 0; i < 9; i++) pW[i] = *(const float4*)&w[wr[i] * CH + cW[i]];
    {
        half* Xs = (half*)sm; half* Ws = (half*)(sm + 7168);
#pragma unroll
        for (int i = 0; i < 3; i++) { half2* d = (half2*)&Xs[rX[i] * 56 + cX[i]];
            d[0] = __floats2half2_rn(pX[i].x, pX[i].y); d[1] = __floats2half2_rn(pX[i].z, pX[i].w); }
#pragma unroll
        for (int i = 0; i < 9; i++) { half2* d = (half2*)&Ws[rW[i] * 56 + cW[i]];
            d[0] = __floats2half2_rn(pW[i].x, pW[i].y); d[1] = __floats2half2_rn(pW[i].z, pW[i].w); }
    }

    float cfr[2][6][4];
#pragma unroll
    for (int mt = 0; mt < 2; mt++)
#pragma unroll
        for (int nt = 0; nt < 6; nt++)
#pragma unroll
            for (int q = 0; q < 4; q++) cfr[mt][nt][q] = 0.f;

#pragma unroll 1
    for (int ch = 0; ch < 16; ch++) {
        __syncthreads();
        if (ch < 15) {
#pragma unroll
            for (int i = 0; i < 3; i++)
                pX[i] = *(const float4*)&x[(b * SEQ + t0 + rX[i]) * CH + (ch + 1) * 48 + cX[i]];
#pragma unroll
            for (int i = 0; i < 9; i++)
                pW[i] = *(const float4*)&w[wr[i] * CH + (ch + 1) * 48 + cW[i]];
        }
        half* Xc = (half*)(sm + (ch & 1) * 28672);
        half* Wc = (half*)(sm + (ch & 1) * 28672 + 7168);
#pragma unroll
        for (int kt = 0; kt < 3; kt++) {
            unsigned int afr[2][4], bfr[6][2];
            int l16 = lane & 15;
#pragma unroll
            for (int mt = 0; mt < 2; mt++)
                ldm_x4(afr[mt], &Xc[(mw * 32 + mt * 16 + l16) * 56 + kt * 16 + ((lane >> 4) << 3)]);
#pragma unroll
            for (int nt = 0; nt < 6; nt++)
                ldm_x2(bfr[nt], &Wc[(nw * 48 + nt * 8 + (l16 & 7)) * 56 + kt * 16 + ((l16 >> 3) << 3)]);
#pragma unroll
            for (int mt = 0; mt < 2; mt++)
#pragma unroll
                for (int nt = 0; nt < 6; nt++)
                    mma16816(cfr[mt][nt], afr[mt], bfr[nt]);
        }
        if (ch < 15) {
            half* Xn = (half*)(sm + ((ch + 1) & 1) * 28672);
            half* Wn = (half*)(sm + ((ch + 1) & 1) * 28672 + 7168);
#pragma unroll
            for (int i = 0; i < 3; i++) { half2* d = (half2*)&Xn[rX[i] * 56 + cX[i]];
                d[0] = __floats2half2_rn(pX[i].x, pX[i].y); d[1] = __floats2half2_rn(pX[i].z, pX[i].w); }
#pragma unroll
            for (int i = 0; i < 9; i++) { half2* d = (half2*)&Wn[rW[i] * 56 + cW[i]];
                d[0] = __floats2half2_rn(pW[i].x, pW[i].y); d[1] = __floats2half2_rn(pW[i].z, pW[i].w); }
        }
    }

    half* qoh = (half*)(dout + QOFF);
    half* kh  = (half*)(dout + KOFF);
    half* vth = (half*)(dout + VOFF);
#pragma unroll
    for (int mt = 0; mt < 2; mt++)
#pragma unroll
        for (int nt = 0; nt < 6; nt++) {
            int row = mw * 32 + mt * 16 + (lane >> 2);
            int col = nw * 48 + nt * 8 + ((lane & 3) << 1);
            int typ = col >> 6, dim = col & 63;
#pragma unroll
            for (int rr = 0; rr < 2; rr++) {
                int tok = t0 + row + rr * 8;
                float v0 = cfr[mt][nt][rr * 2], v1 = cfr[mt][nt][rr * 2 + 1];
                if (typ == 0) {
                    *(half2*)&qoh[(b * SEQ + tok) * CH + grp * 384 + hg * 64 + dim] =
                        __floats2half2_rn(v0 * 0.125f, v1 * 0.125f);
                } else if (typ == 1) {
                    *(half2*)&kh[(bhg * SEQ + tok) * 64 + dim] = __floats2half2_rn(v0, v1);
                } else {
                    vth[(bhg * 64 + dim) * SEQ + tok]     = __float2half(v0);
                    vth[(bhg * 64 + dim + 1) * SEQ + tok] = __float2half(v1);
                }
            }
        }
}

// ============ K2: attention — 128 threads / 64 q-rows (4 CTAs/SM) ============
__global__ __launch_bounds__(128) void attn_kernel(char* __restrict__ dout, int grp)
{
    extern __shared__ __align__(16) char sm[];
    half* Qs = (half*)sm;                                        // [64][72]
    half* Kb[2] = { (half*)(sm + 9216),  (half*)(sm + 18432) };  // [64][72]
    half* Vb[2] = { (half*)(sm + 27648), (half*)(sm + 36864) };  // [64][72] (V^T)

    int tid = threadIdx.x, warp = tid >> 5, lane = tid & 31;
    int bhg = blockIdx.y, b = bhg / 6, hg = bhg % 6;
    int q0 = blockIdx.x * 64;
    half* qoh = (half*)(dout + QOFF);
    const half* kh  = (const half*)(dout + KOFF);
    const half* vth = (const half*)(dout + VOFF);

    // Staging coords: 4 lines each for K and V; line i at row r0s+16i, col c0s
    int r0s = tid >> 3, c0s = (tid & 7) << 3;
    const half* kg[4]; const half* vg[4];
#pragma unroll
    for (int i = 0; i < 4; i++) {
        kg[i] = &kh[(bhg * SEQ + r0s + 16 * i) * 64 + c0s];
        vg[i] = &vth[(bhg * 64 + r0s + 16 * i) * SEQ + c0s];
    }

    // Stage Q (64 rows x 64 halves = 512 uint4 over 128 threads)
#pragma unroll
    for (int i = 0; i < 4; i++) {
        int r = r0s + 16 * i, c = tid & 7;
        ((uint4*)&Qs[r * 72])[c] =
            ((const uint4*)&qoh[(b * SEQ + q0 + r) * CH + grp * 384 + hg * 64])[c];
    }
#pragma unroll
    for (int i = 0; i < 4; i++) {
        cp16(&Kb[0][(r0s + 16 * i) * 72 + c0s], kg[i]);
        cp16(&Vb[0][(r0s + 16 * i) * 72 + c0s], vg[i]);
    }
    CP_COMMIT(); CP_WAIT0();
    __syncthreads();

    unsigned int qA[4][4];
#pragma unroll
    for (int kt = 0; kt < 4; kt++)
        ldm_x4(qA[kt], &Qs[(warp * 16 + (lane & 15)) * 72 + kt * 16 + ((lane >> 4) << 3)]);

    float mrow[2] = {-1e30f, -1e30f}, lrow[2] = {0.f, 0.f}, ofr[8][4];
#pragma unroll
    for (int nt = 0; nt < 8; nt++)
#pragma unroll
        for (int q = 0; q < 4; q++) ofr[nt][q] = 0.f;

    int g = lane >> 3;
#pragma unroll 1
    for (int it = 0; it < 32; it++) {
        __syncthreads();
        if (it < 31) {
            int kadv = (it + 1) * 64 * 64;
            int vadv = (it + 1) * 64;
            half* Kn = Kb[(it + 1) & 1]; half* Vn = Vb[(it + 1) & 1];
#pragma unroll
            for (int i = 0; i < 4; i++) {
                cp16(&Kn[(r0s + 16 * i) * 72 + c0s], kg[i] + kadv);
                cp16(&Vn[(r0s + 16 * i) * 72 + c0s], vg[i] + vadv);
            }
            CP_COMMIT();
        }
        half* Kc = Kb[it & 1]; half* Vc = Vb[it & 1];

        float sfr[8][4];
#pragma unroll
        for (int nt = 0; nt < 8; nt++)
#pragma unroll
            for (int q = 0; q < 4; q++) sfr[nt][q] = 0.f;
#pragma unroll
        for (int kt = 0; kt < 4; kt++) {
            unsigned int bfr[8][2];
#pragma unroll
            for (int np = 0; np < 4; np++) {
                unsigned int r4[4];
                ldm_x4(r4, &Kc[(np * 16 + (g & 1) * 8 + (lane & 7)) * 72 + kt * 16 + ((g >> 1) << 3)]);
                bfr[2 * np][0] = r4[0];     bfr[2 * np][1] = r4[2];
                bfr[2 * np + 1][0] = r4[1]; bfr[2 * np + 1][1] = r4[3];
            }
#pragma unroll
            for (int nt = 0; nt < 8; nt++) mma16816(sfr[nt], qA[kt], bfr[nt]);
        }
#pragma unroll
        for (int hf = 0; hf < 2; hf++) {
            float t8[8];
#pragma unroll
            for (int nt = 0; nt < 8; nt++)
                t8[nt] = fmaxf(sfr[nt][hf * 2], sfr[nt][hf * 2 + 1]);
            float t4a = fmaxf(t8[0], t8[1]), t4b = fmaxf(t8[2], t8[3]);
            float t4c = fmaxf(t8[4], t8[5]), t4d = fmaxf(t8[6], t8[7]);
            float mx = fmaxf(fmaxf(t4a, t4b), fmaxf(t4c, t4d));
            mx = fmaxf(mx, mrow[hf]);
            mx = fmaxf(mx, __shfl_xor_sync(0xffffffffu, mx, 1));
            mx = fmaxf(mx, __shfl_xor_sync(0xffffffffu, mx, 2));
            float c = __expf(mrow[hf] - mx); mrow[hf] = mx;
            float s8[8];
#pragma unroll
            for (int nt = 0; nt < 8; nt++) {
                float p0 = __expf(sfr[nt][hf * 2] - mx);
                float p1 = __expf(sfr[nt][hf * 2 + 1] - mx);
                sfr[nt][hf * 2] = p0; sfr[nt][hf * 2 + 1] = p1;
                s8[nt] = p0 + p1;
            }
            float sa = (s8[0] + s8[1]) + (s8[2] + s8[3]);
            float sb = (s8[4] + s8[5]) + (s8[6] + s8[7]);
            float sum = sa + sb;
            sum += __shfl_xor_sync(0xffffffffu, sum, 1);
            sum += __shfl_xor_sync(0xffffffffu, sum, 2);
            lrow[hf] = lrow[hf] * c + sum;
#pragma unroll
            for (int nt = 0; nt < 8; nt++) {
                ofr[nt][hf * 2] *= c; ofr[nt][hf * 2 + 1] *= c;
            }
        }
        unsigned int pA[4][4];
#pragma unroll
        for (int kt = 0; kt < 4; kt++) {
            pA[kt][0] = pack_h2(sfr[2 * kt][0], sfr[2 * kt][1]);
            pA[kt][1] = pack_h2(sfr[2 * kt][2], sfr[2 * kt][3]);
            pA[kt][2] = pack_h2(sfr[2 * kt + 1][0], sfr[2 * kt + 1][1]);
            pA[kt][3] = pack_h2(sfr[2 * kt + 1][2], sfr[2 * kt + 1][3]);
        }
#pragma unroll
        for (int kt = 0; kt < 4; kt++) {
            unsigned int bfr[8][2];
#pragma unroll
            for (int np = 0; np < 4; np++) {
                unsigned int r4[4];
                ldm_x4(r4, &Vc[(np * 16 + (g & 1) * 8 + (lane & 7)) * 72 + kt * 16 + ((g >> 1) << 3)]);
                bfr[2 * np][0] = r4[0];     bfr[2 * np][1] = r4[2];
                bfr[2 * np + 1][0] = r4[1]; bfr[2 * np + 1][1] = r4[3];
            }
#pragma unroll
            for (int nt = 0; nt < 8; nt++) mma16816(ofr[nt], pA[kt], bfr[nt]);
        }
        if (it < 31) CP_WAIT0();
    }

    float inv[2] = {1.0f / lrow[0], 1.0f / lrow[1]};
#pragma unroll
    for (int nt = 0; nt < 8; nt++) {
        int row = warp * 16 + (lane >> 2);
        int col = nt * 8 + ((lane & 3) << 1);
#pragma unroll
        for (int rr = 0; rr < 2; rr++) {
            int gt = b * SEQ + q0 + row + rr * 8;
            *(half2*)&qoh[gt * CH + grp * 384 + hg * 64 + col] =
                __floats2half2_rn(ofr[nt][rr * 2] * inv[rr], ofr[nt][rr * 2 + 1] * inv[rr]);
        }
    }
}

// ============ K3: out-proj, 64x64 tiles (PROVEN R14: 16 stages, 48-wide) ======
__global__ __launch_bounds__(256) void outproj_kernel(
    const float* __restrict__ pw, const float* __restrict__ bias,
    char* __restrict__ dout, int rowBeg, int rowEnd)
{
    extern __shared__ __align__(16) char sm[];
    half*  Oh = (half*)sm;                 // [64][776] = 99328 B
    float* bs = (float*)(sm + 113664);     // [64]

    int tid = threadIdx.x, warp = tid >> 5, lane = tid & 31;
    int mw = warp >> 2, nw = warp & 3;
    int r0 = rowBeg + blockIdx.x * 64;
    int c0 = blockIdx.y * 64;
    const half* qo = (const half*)(dout + QOFF);
    float* out = (float*)dout;

#pragma unroll
    for (int i = 0; i < 24; i++) {
        int e = tid + 256 * i; int r = e / 96, c = e % 96;
        int rr = r0 + r; if (rr > NTOK - 1) rr = NTOK - 1;
        ((uint4*)&Oh[r * 776])[c] = ((const uint4*)&qo[rr * CH])[c];
    }
    if (tid < 64) bs[tid] = bias[c0 + tid];

    int rP[3], cP[3];
#pragma unroll
    for (int i = 0; i < 3; i++) { int e = tid + 256 * i; rP[i] = e / 12; cP[i] = (e % 12) << 2; }

    float4 pg[3];
#pragma unroll
    for (int i = 0; i < 3; i++) pg[i] = *(const float4*)&pw[(c0 + rP[i]) * CH + cP[i]];
    {
        half* P0 = (half*)(sm + 99328);
#pragma unroll
        for (int i = 0; i < 3; i++) { half2* d = (half2*)&P0[rP[i] * 56 + cP[i]];
            d[0] = __floats2half2_rn(pg[i].x, pg[i].y); d[1] = __floats2half2_rn(pg[i].z, pg[i].w); }
    }

    float cfr[2][2][4];
#pragma unroll
    for (int mt = 0; mt < 2; mt++)
#pragma unroll
        for (int nt = 0; nt < 2; nt++)
#pragma unroll
            for (int q = 0; q < 4; q++) cfr[mt][nt][q] = 0.f;

#pragma unroll 1
    for (int s = 0; s < 16; s++) {
        __syncthreads();
        if (s < 15) {
#pragma unroll
            for (int i = 0; i < 3; i++)
                pg[i] = *(const float4*)&pw[(c0 + rP[i]) * CH + (s + 1) * 48 + cP[i]];
        }
        half* Pc = (half*)(sm + 99328 + (s & 1) * 7168);
#pragma unroll
        for (int kt = 0; kt < 3; kt++) {
            unsigned int afr[2][4], bfr[2][2];
            int l16 = lane & 15;
#pragma unroll
            for (int mt = 0; mt < 2; mt++)
                ldm_x4(afr[mt], &Oh[(mw * 32 + mt * 16 + l16) * 776 + s * 48 + kt * 16 + ((lane >> 4) << 3)]);
#pragma unroll
            for (int nt = 0; nt < 2; nt++)
                ldm_x2(bfr[nt], &Pc[(nw * 16 + nt * 8 + (l16 & 7)) * 56 + kt * 16 + ((l16 >> 3) << 3)]);
#pragma unroll
            for (int mt = 0; mt < 2; mt++)
#pragma unroll
                for (int nt = 0; nt < 2; nt++)
                    mma16816(cfr[mt][nt], afr[mt], bfr[nt]);
        }
        if (s < 15) {
            half* Pn = (half*)(sm + 99328 + ((s + 1) & 1) * 7168);
#pragma unroll
            for (int i = 0; i < 3; i++) { half2* d = (half2*)&Pn[rP[i] * 56 + cP[i]];
                d[0] = __floats2half2_rn(pg[i].x, pg[i].y); d[1] = __floats2half2_rn(pg[i].z, pg[i].w); }
        }
    }

#pragma unroll
    for (int mt = 0; mt < 2; mt++)
#pragma unroll
        for (int nt = 0; nt < 2; nt++) {
            int row = mw * 32 + mt * 16 + (lane >> 2);
            int col = nw * 16 + nt * 8 + ((lane & 3) << 1);
#pragma unroll
            for (int rr = 0; rr < 2; rr++) {
                int gr = r0 + row + rr * 8;
                if (gr < rowEnd) {
                    float2 st = make_float2(cfr[mt][nt][rr * 2] + bs[col],
                                            cfr[mt][nt][rr * 2 + 1] + bs[col + 1]);
                    *(float2*)&out[gr * CH + c0 + col] = st;
                }
            }
        }
}

// ---------------------------------------------------------------------------
extern "C" void kernel_launch(void* const* d_in, const int* in_sizes, int n_in,
                              void* d_out, int out_size) {
    const float* x = 0; const float* qkv_w = 0;
    const float* proj_w = 0; const float* proj_b = 0;
    for (int i = 0; i < n_in; i++) {
        int s = in_sizes[i];
        const float* p = (const float*)d_in[i];
        if (s == NTOK * CH)        { if (!x) x = p; }
        else if (s == 3 * CH * CH) { if (!qkv_w) qkv_w = p; }
        else if (s == CH * CH)     { if (!proj_w) proj_w = p; }
        else if (s == CH)          { if (!proj_b) proj_b = p; }
    }
    if (!x || !qkv_w || !proj_w || !proj_b) {
        x = (const float*)d_in[0]; qkv_w = (const float*)d_in[1];
        proj_w = (const float*)d_in[2]; proj_b = (const float*)d_in[3];
    }
    char* dout = (char*)d_out;

    static int done = 0;
    if (!done) {
        cudaFuncSetAttribute(qkv_kernel, cudaFuncAttributeMaxDynamicSharedMemorySize, 57344);
        cudaFuncSetAttribute(attn_kernel, cudaFuncAttributeMaxDynamicSharedMemorySize, 46080);
        cudaFuncSetAttribute(outproj_kernel, cudaFuncAttributeMaxDynamicSharedMemorySize, 113920);
        done = 1;
    }

    for (int grp = 0; grp < 2; grp++) {
        qkv_kernel<<<dim3(SEQ / 64, 24), 256, 57344>>>(x, qkv_w, dout, grp);
        attn_kernel<<<dim3(SEQ / 64, 24), 128, 46080>>>(dout, grp);
    }
    const int rs[9] = {0, 4096, 6144, 7168, 7680, 7936, 8064, 8128, 8192};
    for (int i = 0; i < 8; i++) {
        int a = rs[i], bnd = rs[i + 1];
        outproj_kernel<<<dim3((bnd - a) / 64, 12), 256, 113920>>>(proj_w, proj_b, dout, a, bnd);
    }
}

// round 17
// speedup vs baseline: 1.5960x; 1.5960x over previous
#include <cuda_runtime.h>
#include <cuda_fp16.h>
#include <cstdint>
#include <math.h>

#define Bq 4
#define SEQ 2048
#define CH 768
#define NH 12
#define HD 64
#define NTOK (Bq*SEQ)

#define KOFF 0
#define VOFF 6291456
#define QOFF 12582912

__device__ __forceinline__ void ldm_x4(unsigned int* r, const void* p) {
    unsigned int a = (unsigned int)__cvta_generic_to_shared(p);
    asm volatile("ldmatrix.sync.aligned.m8n8.x4.shared.b16 {%0,%1,%2,%3}, [%4];"
                 : "=r"(r[0]), "=r"(r[1]), "=r"(r[2]), "=r"(r[3]) : "r"(a));
}
__device__ __forceinline__ void ldm_x2(unsigned int* r, const void* p) {
    unsigned int a = (unsigned int)__cvta_generic_to_shared(p);
    asm volatile("ldmatrix.sync.aligned.m8n8.x2.shared.b16 {%0,%1}, [%2];"
                 : "=r"(r[0]), "=r"(r[1]) : "r"(a));
}
__device__ __forceinline__ void mma16816(float* c, const unsigned int* a,
                                         const unsigned int* b) {
    asm volatile("mma.sync.aligned.m16n8k16.row.col.f32.f16.f16.f32 "
                 "{%0,%1,%2,%3},{%4,%5,%6,%7},{%8,%9},{%0,%1,%2,%3};"
                 : "+f"(c[0]), "+f"(c[1]), "+f"(c[2]), "+f"(c[3])
                 : "r"(a[0]), "r"(a[1]), "r"(a[2]), "r"(a[3]), "r"(b[0]), "r"(b[1]));
}
__device__ __forceinline__ unsigned int pack_h2(float a, float b) {
    __half2 t = __floats2half2_rn(a, b);
    return *(unsigned int*)&t;
}
__device__ __forceinline__ void cp16(void* dst, const void* src) {
    unsigned int d = (unsigned int)__cvta_generic_to_shared(dst);
    asm volatile("cp.async.ca.shared.global [%0], [%1], 16;" :: "r"(d), "l"(src) : "memory");
}
#define CP_COMMIT() asm volatile("cp.async.commit_group;" ::: "memory")
#define CP_WAIT0()  asm volatile("cp.async.wait_group 0;" ::: "memory")

// ============ K1: QKV projection, one 6-head group (proven R12) ============
__global__ __launch_bounds__(256) void qkv_kernel(
    const float* __restrict__ x, const float* __restrict__ w,
    char* __restrict__ dout, int grp)
{
    extern __shared__ __align__(16) char sm[];
    int tid = threadIdx.x, warp = tid >> 5, lane = tid & 31;
    int mw = warp >> 2, nw = warp & 3;
    int t0 = blockIdx.x * 64;
    int bhg = blockIdx.y, b = bhg / 6, hg = bhg % 6, h = grp * 6 + hg;

    int rX[3], cX[3], rW[9], cW[9], wr[9];
#pragma unroll
    for (int i = 0; i < 3; i++) { int e = tid + 256 * i; rX[i] = e / 12; cX[i] = (e % 12) << 2; }
#pragma unroll
    for (int i = 0; i < 9; i++) {
        int e = tid + 256 * i; int r = e / 12; rW[i] = r; cW[i] = (e % 12) << 2;
        wr[i] = (r < 64) ? (h * HD + r) : (r < 128) ? (CH + h * HD + r - 64)
                                                    : (2 * CH + h * HD + r - 128);
    }

    float4 pX[3], pW[9];
#pragma unroll
    for (int i = 0; i < 3; i++) pX[i] = *(const float4*)&x[(b * SEQ + t0 + rX[i]) * CH + cX[i]];
#pragma unroll
    for (int i = 0; i < 9; i++) pW[i] = *(const float4*)&w[wr[i] * CH + cW[i]];
    {
        half* Xs = (half*)sm; half* Ws = (half*)(sm + 7168);
#pragma unroll
        for (int i = 0; i < 3; i++) { half2* d = (half2*)&Xs[rX[i] * 56 + cX[i]];
            d[0] = __floats2half2_rn(pX[i].x, pX[i].y); d[1] = __floats2half2_rn(pX[i].z, pX[i].w); }
#pragma unroll
        for (int i = 0; i < 9; i++) { half2* d = (half2*)&Ws[rW[i] * 56 + cW[i]];
            d[0] = __floats2half2_rn(pW[i].x, pW[i].y); d[1] = __floats2half2_rn(pW[i].z, pW[i].w); }
    }

    float cfr[2][6][4];
#pragma unroll
    for (int mt = 0; mt < 2; mt++)
#pragma unroll
        for (int nt = 0; nt < 6; nt++)
#pragma unroll
            for (int q = 0; q < 4; q++) cfr[mt][nt][q] = 0.f;

#pragma unroll 1
    for (int ch = 0; ch < 16; ch++) {
        __syncthreads();
        if (ch < 15) {
#pragma unroll
            for (int i = 0; i < 3; i++)
                pX[i] = *(const float4*)&x[(b * SEQ + t0 + rX[i]) * CH + (ch + 1) * 48 + cX[i]];
#pragma unroll
            for (int i = 0; i < 9; i++)
                pW[i] = *(const float4*)&w[wr[i] * CH + (ch + 1) * 48 + cW[i]];
        }
        half* Xc = (half*)(sm + (ch & 1) * 28672);
        half* Wc = (half*)(sm + (ch & 1) * 28672 + 7168);
#pragma unroll
        for (int kt = 0; kt < 3; kt++) {
            unsigned int afr[2][4], bfr[6][2];
            int l16 = lane & 15;
#pragma unroll
            for (int mt = 0; mt < 2; mt++)
                ldm_x4(afr[mt], &Xc[(mw * 32 + mt * 16 + l16) * 56 + kt * 16 + ((lane >> 4) << 3)]);
#pragma unroll
            for (int nt = 0; nt < 6; nt++)
                ldm_x2(bfr[nt], &Wc[(nw * 48 + nt * 8 + (l16 & 7)) * 56 + kt * 16 + ((l16 >> 3) << 3)]);
#pragma unroll
            for (int mt = 0; mt < 2; mt++)
#pragma unroll
                for (int nt = 0; nt < 6; nt++)
                    mma16816(cfr[mt][nt], afr[mt], bfr[nt]);
        }
        if (ch < 15) {
            half* Xn = (half*)(sm + ((ch + 1) & 1) * 28672);
            half* Wn = (half*)(sm + ((ch + 1) & 1) * 28672 + 7168);
#pragma unroll
            for (int i = 0; i < 3; i++) { half2* d = (half2*)&Xn[rX[i] * 56 + cX[i]];
                d[0] = __floats2half2_rn(pX[i].x, pX[i].y); d[1] = __floats2half2_rn(pX[i].z, pX[i].w); }
#pragma unroll
            for (int i = 0; i < 9; i++) { half2* d = (half2*)&Wn[rW[i] * 56 + cW[i]];
                d[0] = __floats2half2_rn(pW[i].x, pW[i].y); d[1] = __floats2half2_rn(pW[i].z, pW[i].w); }
        }
    }

    half* qoh = (half*)(dout + QOFF);
    half* kh  = (half*)(dout + KOFF);
    half* vth = (half*)(dout + VOFF);
#pragma unroll
    for (int mt = 0; mt < 2; mt++)
#pragma unroll
        for (int nt = 0; nt < 6; nt++) {
            int row = mw * 32 + mt * 16 + (lane >> 2);
            int col = nw * 48 + nt * 8 + ((lane & 3) << 1);
            int typ = col >> 6, dim = col & 63;
#pragma unroll
            for (int rr = 0; rr < 2; rr++) {
                int tok = t0 + row + rr * 8;
                float v0 = cfr[mt][nt][rr * 2], v1 = cfr[mt][nt][rr * 2 + 1];
                if (typ == 0) {
                    *(half2*)&qoh[(b * SEQ + tok) * CH + grp * 384 + hg * 64 + dim] =
                        __floats2half2_rn(v0 * 0.125f, v1 * 0.125f);
                } else if (typ == 1) {
                    *(half2*)&kh[(bhg * SEQ + tok) * 64 + dim] = __floats2half2_rn(v0, v1);
                } else {
                    vth[(bhg * 64 + dim) * SEQ + tok]     = __float2half(v0);
                    vth[(bhg * 64 + dim + 1) * SEQ + tok] = __float2half(v1);
                }
            }
        }
}

// ============ K2: attention (PROVEN R15: 256 thr, cp.async, tree red) ========
__global__ __launch_bounds__(256) void attn_kernel(char* __restrict__ dout, int grp)
{
    extern __shared__ __align__(16) char sm[];
    half* Qs = (half*)sm;
    half* Kb[2] = { (half*)(sm + 18432), (half*)(sm + 27648) };
    half* Vb[2] = { (half*)(sm + 36864), (half*)(sm + 46080) };

    int tid = threadIdx.x, warp = tid >> 5, lane = tid & 31;
    int bhg = blockIdx.y, b = bhg / 6, hg = bhg % 6;
    int q0 = blockIdx.x * 128;
    half* qoh = (half*)(dout + QOFF);
    const half* kh  = (const half*)(dout + KOFF);
    const half* vth = (const half*)(dout + VOFF);

    int r0s = tid >> 3, c0s = (tid & 7) << 3;
    int r1s = (tid + 256) >> 3, c1s = c0s;
    const half* kg0 = &kh[(bhg * SEQ + r0s) * 64 + c0s];
    const half* kg1 = &kh[(bhg * SEQ + r1s) * 64 + c0s];
    const half* vg0 = &vth[(bhg * 64 + r0s) * SEQ + c0s];
    const half* vg1 = &vth[(bhg * 64 + r1s) * SEQ + c0s];

#pragma unroll
    for (int i = 0; i < 4; i++) {
        int e = tid + 256 * i; int r = e >> 3, c = e & 7;
        ((uint4*)&Qs[r * 72])[c] =
            ((const uint4*)&qoh[(b * SEQ + q0 + r) * CH + grp * 384 + hg * 64])[c];
    }
    cp16(&Kb[0][r0s * 72 + c0s], kg0);
    cp16(&Kb[0][r1s * 72 + c1s], kg1);
    cp16(&Vb[0][r0s * 72 + c0s], vg0);
    cp16(&Vb[0][r1s * 72 + c1s], vg1);
    CP_COMMIT(); CP_WAIT0();
    __syncthreads();

    unsigned int qA[4][4];
#pragma unroll
    for (int kt = 0; kt < 4; kt++)
        ldm_x4(qA[kt], &Qs[(warp * 16 + (lane & 15)) * 72 + kt * 16 + ((lane >> 4) << 3)]);

    float mrow[2] = {-1e30f, -1e30f}, lrow[2] = {0.f, 0.f}, ofr[8][4];
#pragma unroll
    for (int nt = 0; nt < 8; nt++)
#pragma unroll
        for (int q = 0; q < 4; q++) ofr[nt][q] = 0.f;

    int g = lane >> 3;
#pragma unroll 1
    for (int it = 0; it < 32; it++) {
        __syncthreads();
        if (it < 31) {
            int kadv = (it + 1) * 64 * 64;
            int vadv = (it + 1) * 64;
            half* Kn = Kb[(it + 1) & 1]; half* Vn = Vb[(it + 1) & 1];
            cp16(&Kn[r0s * 72 + c0s], kg0 + kadv);
            cp16(&Kn[r1s * 72 + c1s], kg1 + kadv);
            cp16(&Vn[r0s * 72 + c0s], vg0 + vadv);
            cp16(&Vn[r1s * 72 + c1s], vg1 + vadv);
            CP_COMMIT();
        }
        half* Kc = Kb[it & 1]; half* Vc = Vb[it & 1];

        float sfr[8][4];
#pragma unroll
        for (int nt = 0; nt < 8; nt++)
#pragma unroll
            for (int q = 0; q < 4; q++) sfr[nt][q] = 0.f;
#pragma unroll
        for (int kt = 0; kt < 4; kt++) {
            unsigned int bfr[8][2];
#pragma unroll
            for (int np = 0; np < 4; np++) {
                unsigned int r4[4];
                ldm_x4(r4, &Kc[(np * 16 + (g & 1) * 8 + (lane & 7)) * 72 + kt * 16 + ((g >> 1) << 3)]);
                bfr[2 * np][0] = r4[0];     bfr[2 * np][1] = r4[2];
                bfr[2 * np + 1][0] = r4[1]; bfr[2 * np + 1][1] = r4[3];
            }
#pragma unroll
            for (int nt = 0; nt < 8; nt++) mma16816(sfr[nt], qA[kt], bfr[nt]);
        }
#pragma unroll
        for (int hf = 0; hf < 2; hf++) {
            float t8[8];
#pragma unroll
            for (int nt = 0; nt < 8; nt++)
                t8[nt] = fmaxf(sfr[nt][hf * 2], sfr[nt][hf * 2 + 1]);
            float t4a = fmaxf(t8[0], t8[1]), t4b = fmaxf(t8[2], t8[3]);
            float t4c = fmaxf(t8[4], t8[5]), t4d = fmaxf(t8[6], t8[7]);
            float mx = fmaxf(fmaxf(t4a, t4b), fmaxf(t4c, t4d));
            mx = fmaxf(mx, mrow[hf]);
            mx = fmaxf(mx, __shfl_xor_sync(0xffffffffu, mx, 1));
            mx = fmaxf(mx, __shfl_xor_sync(0xffffffffu, mx, 2));
            float c = __expf(mrow[hf] - mx); mrow[hf] = mx;
            float s8[8];
#pragma unroll
            for (int nt = 0; nt < 8; nt++) {
                float p0 = __expf(sfr[nt][hf * 2] - mx);
                float p1 = __expf(sfr[nt][hf * 2 + 1] - mx);
                sfr[nt][hf * 2] = p0; sfr[nt][hf * 2 + 1] = p1;
                s8[nt] = p0 + p1;
            }
            float sa = (s8[0] + s8[1]) + (s8[2] + s8[3]);
            float sb = (s8[4] + s8[5]) + (s8[6] + s8[7]);
            float sum = sa + sb;
            sum += __shfl_xor_sync(0xffffffffu, sum, 1);
            sum += __shfl_xor_sync(0xffffffffu, sum, 2);
            lrow[hf] = lrow[hf] * c + sum;
#pragma unroll
            for (int nt = 0; nt < 8; nt++) {
                ofr[nt][hf * 2] *= c; ofr[nt][hf * 2 + 1] *= c;
            }
        }
        unsigned int pA[4][4];
#pragma unroll
        for (int kt = 0; kt < 4; kt++) {
            pA[kt][0] = pack_h2(sfr[2 * kt][0], sfr[2 * kt][1]);
            pA[kt][1] = pack_h2(sfr[2 * kt][2], sfr[2 * kt][3]);
            pA[kt][2] = pack_h2(sfr[2 * kt + 1][0], sfr[2 * kt + 1][1]);
            pA[kt][3] = pack_h2(sfr[2 * kt + 1][2], sfr[2 * kt + 1][3]);
        }
#pragma unroll
        for (int kt = 0; kt < 4; kt++) {
            unsigned int bfr[8][2];
#pragma unroll
            for (int np = 0; np < 4; np++) {
                unsigned int r4[4];
                ldm_x4(r4, &Vc[(np * 16 + (g & 1) * 8 + (lane & 7)) * 72 + kt * 16 + ((g >> 1) << 3)]);
                bfr[2 * np][0] = r4[0];     bfr[2 * np][1] = r4[2];
                bfr[2 * np + 1][0] = r4[1]; bfr[2 * np + 1][1] = r4[3];
            }
#pragma unroll
            for (int nt = 0; nt < 8; nt++) mma16816(ofr[nt], pA[kt], bfr[nt]);
        }
        if (it < 31) CP_WAIT0();
    }

    float inv[2] = {1.0f / lrow[0], 1.0f / lrow[1]};
#pragma unroll
    for (int nt = 0; nt < 8; nt++) {
        int row = warp * 16 + (lane >> 2);
        int col = nt * 8 + ((lane & 3) << 1);
#pragma unroll
        for (int rr = 0; rr < 2; rr++) {
            int gt = b * SEQ + q0 + row + rr * 8;
            *(half2*)&qoh[gt * CH + grp * 384 + hg * 64 + col] =
                __floats2half2_rn(ofr[nt][rr * 2] * inv[rr], ofr[nt][rr * 2 + 1] * inv[rr]);
        }
    }
}

// ============ K3: out-proj, 64x64 tiles (PROVEN R14: 16 stages, 48-wide) ======
__global__ __launch_bounds__(256) void outproj_kernel(
    const float* __restrict__ pw, const float* __restrict__ bias,
    char* __restrict__ dout, int rowBeg, int rowEnd)
{
    extern __shared__ __align__(16) char sm[];
    half*  Oh = (half*)sm;                 // [64][776] = 99328 B
    float* bs = (float*)(sm + 113664);     // [64]

    int tid = threadIdx.x, warp = tid >> 5, lane = tid & 31;
    int mw = warp >> 2, nw = warp & 3;
    int r0 = rowBeg + blockIdx.x * 64;
    int c0 = blockIdx.y * 64;
    const half* qo = (const half*)(dout + QOFF);
    float* out = (float*)dout;

#pragma unroll
    for (int i = 0; i < 24; i++) {
        int e = tid + 256 * i; int r = e / 96, c = e % 96;
        int rr = r0 + r; if (rr > NTOK - 1) rr = NTOK - 1;
        ((uint4*)&Oh[r * 776])[c] = ((const uint4*)&qo[rr * CH])[c];
    }
    if (tid < 64) bs[tid] = bias[c0 + tid];

    int rP[3], cP[3];
#pragma unroll
    for (int i = 0; i < 3; i++) { int e = tid + 256 * i; rP[i] = e / 12; cP[i] = (e % 12) << 2; }

    float4 pg[3];
#pragma unroll
    for (int i = 0; i < 3; i++) pg[i] = *(const float4*)&pw[(c0 + rP[i]) * CH + cP[i]];
    {
        half* P0 = (half*)(sm + 99328);
#pragma unroll
        for (int i = 0; i < 3; i++) { half2* d = (half2*)&P0[rP[i] * 56 + cP[i]];
            d[0] = __floats2half2_rn(pg[i].x, pg[i].y); d[1] = __floats2half2_rn(pg[i].z, pg[i].w); }
    }

    float cfr[2][2][4];
#pragma unroll
    for (int mt = 0; mt < 2; mt++)
#pragma unroll
        for (int nt = 0; nt < 2; nt++)
#pragma unroll
            for (int q = 0; q < 4; q++) cfr[mt][nt][q] = 0.f;

#pragma unroll 1
    for (int s = 0; s < 16; s++) {
        __syncthreads();
        if (s < 15) {
#pragma unroll
            for (int i = 0; i < 3; i++)
                pg[i] = *(const float4*)&pw[(c0 + rP[i]) * CH + (s + 1) * 48 + cP[i]];
        }
        half* Pc = (half*)(sm + 99328 + (s & 1) * 7168);
#pragma unroll
        for (int kt = 0; kt < 3; kt++) {
            unsigned int afr[2][4], bfr[2][2];
            int l16 = lane & 15;
#pragma unroll
            for (int mt = 0; mt < 2; mt++)
                ldm_x4(afr[mt], &Oh[(mw * 32 + mt * 16 + l16) * 776 + s * 48 + kt * 16 + ((lane >> 4) << 3)]);
#pragma unroll
            for (int nt = 0; nt < 2; nt++)
                ldm_x2(bfr[nt], &Pc[(nw * 16 + nt * 8 + (l16 & 7)) * 56 + kt * 16 + ((l16 >> 3) << 3)]);
#pragma unroll
            for (int mt = 0; mt < 2; mt++)
#pragma unroll
                for (int nt = 0; nt < 2; nt++)
                    mma16816(cfr[mt][nt], afr[mt], bfr[nt]);
        }
        if (s < 15) {
            half* Pn = (half*)(sm + 99328 + ((s + 1) & 1) * 7168);
#pragma unroll
            for (int i = 0; i < 3; i++) { half2* d = (half2*)&Pn[rP[i] * 56 + cP[i]];
                d[0] = __floats2half2_rn(pg[i].x, pg[i].y); d[1] = __floats2half2_rn(pg[i].z, pg[i].w); }
        }
    }

#pragma unroll
    for (int mt = 0; mt < 2; mt++)
#pragma unroll
        for (int nt = 0; nt < 2; nt++) {
            int row = mw * 32 + mt * 16 + (lane >> 2);
            int col = nw * 16 + nt * 8 + ((lane & 3) << 1);
#pragma unroll
            for (int rr = 0; rr < 2; rr++) {
                int gr = r0 + row + rr * 8;
                if (gr < rowEnd) {
                    float2 st = make_float2(cfr[mt][nt][rr * 2] + bs[col],
                                            cfr[mt][nt][rr * 2 + 1] + bs[col + 1]);
                    *(float2*)&out[gr * CH + c0 + col] = st;
                }
            }
        }
}

// ---------------------------------------------------------------------------
extern "C" void kernel_launch(void* const* d_in, const int* in_sizes, int n_in,
                              void* d_out, int out_size) {
    const float* x = 0; const float* qkv_w = 0;
    const float* proj_w = 0; const float* proj_b = 0;
    for (int i = 0; i < n_in; i++) {
        int s = in_sizes[i];
        const float* p = (const float*)d_in[i];
        if (s == NTOK * CH)        { if (!x) x = p; }
        else if (s == 3 * CH * CH) { if (!qkv_w) qkv_w = p; }
        else if (s == CH * CH)     { if (!proj_w) proj_w = p; }
        else if (s == CH)          { if (!proj_b) proj_b = p; }
    }
    if (!x || !qkv_w || !proj_w || !proj_b) {
        x = (const float*)d_in[0]; qkv_w = (const float*)d_in[1];
        proj_w = (const float*)d_in[2]; proj_b = (const float*)d_in[3];
    }
    char* dout = (char*)d_out;

    static int done = 0;
    if (!done) {
        cudaFuncSetAttribute(qkv_kernel, cudaFuncAttributeMaxDynamicSharedMemorySize, 57344);
        cudaFuncSetAttribute(attn_kernel, cudaFuncAttributeMaxDynamicSharedMemorySize, 55296);
        cudaFuncSetAttribute(outproj_kernel, cudaFuncAttributeMaxDynamicSharedMemorySize, 113920);
        done = 1;
    }

    for (int grp = 0; grp < 2; grp++) {
        qkv_kernel<<<dim3(SEQ / 64, 24), 256, 57344>>>(x, qkv_w, dout, grp);
        attn_kernel<<<dim3(SEQ / 128, 24), 256, 55296>>>(dout, grp);
    }
    const int rs[9] = {0, 4096, 6144, 7168, 7680, 7936, 8064, 8128, 8192};
    for (int i = 0; i < 8; i++) {
        int a = rs[i], bnd = rs[i + 1];
        outproj_kernel<<<dim3((bnd - a) / 64, 12), 256, 113920>>>(proj_w, proj_b, dout, a, bnd);
    }
}